// round 1
// baseline (speedup 1.0000x reference)
#include <cuda_runtime.h>
#include <math.h>

// Problem constants (match reference)
#define B_DIM 4096
#define K_DIM 512
#define T_DIM 30
#define NTH   256          // threads per CTA in kernel 1; each handles 2 candidates
#define NWARP (NTH / 32)
#define MAX_GUESSES 6
#define MISS_THRESH 2.0f

// Scratch for per-sample losses (device global; no runtime allocation).
__device__ float g_loss[B_DIM];

__global__ __launch_bounds__(NTH)
void score_classify_kernel(const float* __restrict__ out_scores,   // [B*K, 1]
                           const float* __restrict__ pred_cand,    // [B, K, T, 2]
                           const float* __restrict__ pred_gt,      // [B, T, 2]
                           const float* __restrict__ scales)       // [B]
{
    const int b  = blockIdx.x;
    const int t  = threadIdx.x;
    const int k0 = t;
    const int k1 = t + NTH;
    const int lane = t & 31;
    const int w    = t >> 5;

    __shared__ float sA[NWARP], sB[NWARP];              // max-pass
    __shared__ float sS0[NWARP], sS1[NWARP], sS2[NWARP]; // sum-pass
    __shared__ float sV[NWARP], sF[NWARP];              // argmax passes
    __shared__ int   sI[NWARP];
    __shared__ float bc[4];                             // broadcast slots

    // ---- loads (the only heavy DRAM traffic) ----
    const float2 g = *reinterpret_cast<const float2*>(
        pred_gt + ((size_t)b * T_DIM + (T_DIM - 1)) * 2);
    const float sc = scales[b];

    const float* ob = out_scores + (size_t)b * K_DIM;
    float o0 = ob[k0];
    float o1 = ob[k1];

    const size_t base = (((size_t)b * K_DIM) * T_DIM + (T_DIM - 1)) * 2;
    const float2 c0 = *reinterpret_cast<const float2*>(pred_cand + base + (size_t)k0 * (T_DIM * 2));
    const float2 c1 = *reinterpret_cast<const float2*>(pred_cand + base + (size_t)k1 * (T_DIM * 2));

    float dx = c0.x - g.x, dy = c0.y - g.y;
    const float f0 = sc * sqrtf(dx * dx + dy * dy);   // fde for k0
    dx = c1.x - g.x;  dy = c1.y - g.y;
    const float f1 = sc * sqrtf(dx * dx + dy * dy);   // fde for k1

    // ---- pass A: fused max of score(=-fde) and max of out ----
    float ms = fmaxf(-f0, -f1);
    float mo = fmaxf(o0, o1);
    #pragma unroll
    for (int off = 16; off; off >>= 1) {
        ms = fmaxf(ms, __shfl_xor_sync(0xffffffffu, ms, off));
        mo = fmaxf(mo, __shfl_xor_sync(0xffffffffu, mo, off));
    }
    if (lane == 0) { sA[w] = ms; sB[w] = mo; }
    __syncthreads();
    if (t < 32) {
        ms = (t < NWARP) ? sA[t] : -3.4e38f;
        mo = (t < NWARP) ? sB[t] : -3.4e38f;
        #pragma unroll
        for (int off = 16; off; off >>= 1) {
            ms = fmaxf(ms, __shfl_xor_sync(0xffffffffu, ms, off));
            mo = fmaxf(mo, __shfl_xor_sync(0xffffffffu, mo, off));
        }
        if (t == 0) { bc[0] = ms; bc[1] = mo; }
    }
    __syncthreads();
    const float MS = bc[0];   // max score
    const float MO = bc[1];   // max out

    // ---- pass B: fused 3 sums: Zs, Zo, S = sum e^{s-MS}*out ----
    const float e0 = expf(-f0 - MS), e1 = expf(-f1 - MS);
    float zs = e0 + e1;
    float zo = expf(o0 - MO) + expf(o1 - MO);
    float ss = e0 * o0 + e1 * o1;
    #pragma unroll
    for (int off = 16; off; off >>= 1) {
        zs += __shfl_xor_sync(0xffffffffu, zs, off);
        zo += __shfl_xor_sync(0xffffffffu, zo, off);
        ss += __shfl_xor_sync(0xffffffffu, ss, off);
    }
    if (lane == 0) { sS0[w] = zs; sS1[w] = zo; sS2[w] = ss; }
    __syncthreads();
    if (t < 32) {
        zs = (t < NWARP) ? sS0[t] : 0.f;
        zo = (t < NWARP) ? sS1[t] : 0.f;
        ss = (t < NWARP) ? sS2[t] : 0.f;
        #pragma unroll
        for (int off = 16; off; off >>= 1) {
            zs += __shfl_xor_sync(0xffffffffu, zs, off);
            zo += __shfl_xor_sync(0xffffffffu, zo, off);
            ss += __shfl_xor_sync(0xffffffffu, ss, off);
        }
        if (t == 0) { bc[0] = zs; bc[1] = zo; bc[2] = ss; }
    }
    __syncthreads();
    const float Zs = bc[0], Zo = bc[1], Ssum = bc[2];

    // cls = lse(out) - sum(tgt*out) = MO + log(Zo) - S/Zs
    const float cls = MO + logf(Zo) - Ssum / Zs;

    // ---- top-6 of out via 6 iterative block argmaxes; min fde over winners ----
    float minF = 3.4e38f;
    for (int r = 0; r < MAX_GUESSES; r++) {
        float lv; int li; float lf;
        if (o0 > o1 || (o0 == o1 && k0 < k1)) { lv = o0; li = k0; lf = f0; }
        else                                   { lv = o1; li = k1; lf = f1; }
        #pragma unroll
        for (int off = 16; off; off >>= 1) {
            float v2 = __shfl_xor_sync(0xffffffffu, lv, off);
            int   i2 = __shfl_xor_sync(0xffffffffu, li, off);
            float f2 = __shfl_xor_sync(0xffffffffu, lf, off);
            if (v2 > lv || (v2 == lv && i2 < li)) { lv = v2; li = i2; lf = f2; }
        }
        if (lane == 0) { sV[w] = lv; sI[w] = li; sF[w] = lf; }
        __syncthreads();
        if (t < 32) {
            lv = (t < NWARP) ? sV[t] : -3.4e38f;
            li = (t < NWARP) ? sI[t] : 0x7fffffff;
            lf = (t < NWARP) ? sF[t] : 0.f;
            #pragma unroll
            for (int off = 16; off; off >>= 1) {
                float v2 = __shfl_xor_sync(0xffffffffu, lv, off);
                int   i2 = __shfl_xor_sync(0xffffffffu, li, off);
                float f2 = __shfl_xor_sync(0xffffffffu, lf, off);
                if (v2 > lv || (v2 == lv && i2 < li)) { lv = v2; li = i2; lf = f2; }
            }
            if (t == 0) { bc[0] = lf; bc[1] = __int_as_float(li); }
        }
        __syncthreads();
        const float wf = bc[0];
        const int   wi = __float_as_int(bc[1]);
        minF = fminf(minF, wf);
        if (wi == k0) o0 = -3.4e38f;
        if (wi == k1) o1 = -3.4e38f;
        __syncthreads();   // smem reuse hazard between iterations
    }

    if (t == 0) {
        const float miss = fmaxf(minF - MISS_THRESH, 0.0f);
        g_loss[b] = cls + miss;
    }
}

__global__ __launch_bounds__(1024)
void final_reduce_kernel(float* __restrict__ out)
{
    const int t = threadIdx.x;
    __shared__ float sm[32];
    float s = g_loss[t] + g_loss[t + 1024] + g_loss[t + 2048] + g_loss[t + 3072];
    #pragma unroll
    for (int off = 16; off; off >>= 1)
        s += __shfl_xor_sync(0xffffffffu, s, off);
    if ((t & 31) == 0) sm[t >> 5] = s;
    __syncthreads();
    if (t < 32) {
        s = sm[t];
        #pragma unroll
        for (int off = 16; off; off >>= 1)
            s += __shfl_xor_sync(0xffffffffu, s, off);
        if (t == 0) out[0] = s * (1.0f / (float)B_DIM);
    }
}

extern "C" void kernel_launch(void* const* d_in, const int* in_sizes, int n_in,
                              void* d_out, int out_size)
{
    const float* out_scores = (const float*)d_in[0];   // (B*K, 1)
    const float* pred_cand  = (const float*)d_in[1];   // (B, K, T, 2)
    const float* pred_gt    = (const float*)d_in[2];   // (B, T, 2)
    const float* scales     = (const float*)d_in[3];   // (B,)
    float* out = (float*)d_out;

    score_classify_kernel<<<B_DIM, NTH>>>(out_scores, pred_cand, pred_gt, scales);
    final_reduce_kernel<<<1, 1024>>>(out);
}

// round 2
// speedup vs baseline: 1.0716x; 1.0716x over previous
#include <cuda_runtime.h>
#include <math.h>

#define B_DIM 4096
#define K_DIM 512
#define T_DIM 30
#define WARPS_PER_CTA 8
#define NTH (WARPS_PER_CTA * 32)
#define GRID_DIM (B_DIM / WARPS_PER_CTA)   // 512 CTAs
#define CPL 16                              // candidates per lane (512/32)
#define MAX_GUESSES 6
#define MISS_THRESH 2.0f

// Scratch (device globals; no runtime allocation)
__device__ float g_loss[B_DIM];
__device__ unsigned int g_cnt = 0;

// monotone float->u32 transform (total order preserved)
__device__ __forceinline__ unsigned sortable(float x) {
    unsigned u = __float_as_uint(x);
    return u ^ (unsigned)(((int)u >> 31) | 0x80000000);
}

__global__ __launch_bounds__(NTH)
void score_classify_fused(const float* __restrict__ out_scores,   // [B*K,1]
                          const float* __restrict__ pred_cand,    // [B,K,T,2]
                          const float* __restrict__ pred_gt,      // [B,T,2]
                          const float* __restrict__ scales,       // [B]
                          float* __restrict__ out)
{
    const int lane = threadIdx.x & 31;
    const int wid  = threadIdx.x >> 5;
    const int b    = blockIdx.x * WARPS_PER_CTA + wid;

    // per-sample constants (same address across warp -> single broadcast sector)
    const float2 g  = *reinterpret_cast<const float2*>(
        pred_gt + ((size_t)b * T_DIM + (T_DIM - 1)) * 2);
    const float  sc = scales[b];
    const float* ob = out_scores + (size_t)b * K_DIM;
    const float* cb = pred_cand + (((size_t)b * K_DIM) * T_DIM + (T_DIM - 1)) * 2;

    // ---- front-batched loads: MLP=16 strided float2 gather + 16 coalesced ----
    float2 c[CPL];
    float  o[CPL];
    #pragma unroll
    for (int j = 0; j < CPL; j++) {
        const int k = j * 32 + lane;
        o[j] = ob[k];
        c[j] = *reinterpret_cast<const float2*>(cb + (size_t)k * (T_DIM * 2));
    }

    // ---- fde, exp sums (no max-subtraction needed: -f<=0, |o| small) ----
    float    f[CPL];
    unsigned os[CPL];
    float zs = 0.f, zo = 0.f, ss = 0.f;
    #pragma unroll
    for (int j = 0; j < CPL; j++) {
        const float dx = c[j].x - g.x;
        const float dy = c[j].y - g.y;
        f[j] = sc * sqrtf(fmaf(dx, dx, dy * dy));
        const float ef = expf(-f[j]);
        zs += ef;
        ss  = fmaf(ef, o[j], ss);
        zo += expf(o[j]);
        os[j] = sortable(o[j]);
    }

    // ---- warp sums (single butterfly, 3 values fused) ----
    #pragma unroll
    for (int off = 16; off; off >>= 1) {
        zs += __shfl_xor_sync(0xffffffffu, zs, off);
        zo += __shfl_xor_sync(0xffffffffu, zo, off);
        ss += __shfl_xor_sync(0xffffffffu, ss, off);
    }

    // ---- lane-local top-6 of os (descending t0..t5), branchless IMNMX net ----
    unsigned t0 = 0, t1 = 0, t2 = 0, t3 = 0, t4 = 0, t5 = 0;
    #pragma unroll
    for (int j = 0; j < CPL; j++) {
        unsigned x = os[j], a;
        a = max(t0, x); x = min(t0, x); t0 = a;
        a = max(t1, x); x = min(t1, x); t1 = a;
        a = max(t2, x); x = min(t2, x); t2 = a;
        a = max(t3, x); x = min(t3, x); t3 = a;
        a = max(t4, x); x = min(t4, x); t4 = a;
        t5 = max(t5, x);
    }

    // ---- 6 warp pops via REDUX; theta = 6th-largest o (sortable space) ----
    unsigned theta = 0;
    #pragma unroll
    for (int r = 0; r < MAX_GUESSES; r++) {
        const unsigned m = __reduce_max_sync(0xffffffffu, t0);
        theta = m;
        if (t0 == m) { t0 = t1; t1 = t2; t2 = t3; t3 = t4; t4 = t5; t5 = 0; }
    }

    // ---- minFDE among the top-6 set {os >= theta}; f>=0 so raw bits order ----
    float minf = 3.4e38f;
    #pragma unroll
    for (int j = 0; j < CPL; j++)
        if (os[j] >= theta) minf = fminf(minf, f[j]);
    const unsigned mf = __reduce_min_sync(0xffffffffu, __float_as_uint(minf));
    const float minF = __uint_as_float(mf);

    if (lane == 0) {
        const float cls = logf(zo) - ss / zs;
        g_loss[b] = cls + fmaxf(minF - MISS_THRESH, 0.0f);
    }

    // ---- fused deterministic tail reduction (last CTA) ----
    __shared__ bool  s_last;
    __shared__ float sm[WARPS_PER_CTA];
    __syncthreads();
    if (threadIdx.x == 0) {
        __threadfence();
        const unsigned p = atomicAdd(&g_cnt, 1u);
        s_last = (p == (unsigned)(gridDim.x - 1));
    }
    __syncthreads();
    if (s_last) {
        float s = 0.f;
        #pragma unroll
        for (int i = 0; i < B_DIM / NTH; i++)
            s += __ldcg(&g_loss[threadIdx.x + i * NTH]);   // L1-bypass: fresh data
        #pragma unroll
        for (int off = 16; off; off >>= 1)
            s += __shfl_xor_sync(0xffffffffu, s, off);
        if (lane == 0) sm[wid] = s;
        __syncthreads();
        if (threadIdx.x < 32) {
            s = (threadIdx.x < WARPS_PER_CTA) ? sm[threadIdx.x] : 0.f;
            #pragma unroll
            for (int off = 4; off; off >>= 1)
                s += __shfl_xor_sync(0xffffffffu, s, off);
            if (threadIdx.x == 0) {
                out[0] = s * (1.0f / (float)B_DIM);
                g_cnt = 0;   // reset for next graph replay
            }
        }
    }
}

extern "C" void kernel_launch(void* const* d_in, const int* in_sizes, int n_in,
                              void* d_out, int out_size)
{
    const float* out_scores = (const float*)d_in[0];   // (B*K, 1)
    const float* pred_cand  = (const float*)d_in[1];   // (B, K, T, 2)
    const float* pred_gt    = (const float*)d_in[2];   // (B, T, 2)
    const float* scales     = (const float*)d_in[3];   // (B,)
    float* out = (float*)d_out;

    score_classify_fused<<<GRID_DIM, NTH>>>(out_scores, pred_cand, pred_gt, scales, out);
}

// round 3
// speedup vs baseline: 1.0766x; 1.0047x over previous
#include <cuda_runtime.h>
#include <math.h>

#define B_DIM 4096
#define K_DIM 512
#define T_DIM 30
#define WPS   4                     // warps per sample
#define CPL   (K_DIM / (32 * WPS))  // 4 candidates per lane
#define SPC   2                     // samples per CTA (8 warps / WPS)
#define NTH   256
#define GRID_DIM (B_DIM / SPC)      // 2048 CTAs
#define MAX_GUESSES 6
#define MISS_THRESH 2.0f

// Scratch (device globals; no runtime allocation)
__device__ float g_loss[B_DIM];
__device__ unsigned int g_cnt = 0;

// monotone float->u32 transform (total order preserved)
__device__ __forceinline__ unsigned sortable(float x) {
    unsigned u = __float_as_uint(x);
    return u ^ (unsigned)(((int)u >> 31) | 0x80000000);
}

__global__ __launch_bounds__(NTH)
void score_classify_fused(const float* __restrict__ out_scores,   // [B*K,1]
                          const float* __restrict__ pred_cand,    // [B,K,T,2]
                          const float* __restrict__ pred_gt,      // [B,T,2]
                          const float* __restrict__ scales,       // [B]
                          float* __restrict__ out)
{
    const int lane = threadIdx.x & 31;
    const int wid  = threadIdx.x >> 5;     // 0..7
    const int s    = wid / WPS;            // sample slot in CTA (0..1)
    const int ws   = wid % WPS;            // warp index within sample (0..3)
    const int b    = blockIdx.x * SPC + s;

    __shared__ float    sm_sum[SPC][WPS][3];          // zs, zo, ss partials
    __shared__ unsigned sm_top[SPC][WPS][MAX_GUESSES];// per-warp top-6 (desc)
    __shared__ unsigned sm_minf[SPC][WPS];            // per-warp min fde bits

    // per-sample constants (warp-uniform -> broadcast)
    const float2 g  = *reinterpret_cast<const float2*>(
        pred_gt + ((size_t)b * T_DIM + (T_DIM - 1)) * 2);
    const float  sc = scales[b];
    const float* ob = out_scores + (size_t)b * K_DIM;
    const float* cb = pred_cand + (((size_t)b * K_DIM) * T_DIM + (T_DIM - 1)) * 2;

    // ---- front-batched loads: 4 strided float2 gathers + 4 coalesced ----
    float2 c[CPL];
    float  o[CPL];
    #pragma unroll
    for (int j = 0; j < CPL; j++) {
        const int k = (ws * CPL + j) * 32 + lane;
        o[j] = ob[k];
        c[j] = *reinterpret_cast<const float2*>(cb + (size_t)k * (T_DIM * 2));
    }

    // ---- fde + exp partial sums (no max-shift needed: -f<=0, |o| small) ----
    float    f[CPL];
    unsigned os[CPL];
    float zs = 0.f, zo = 0.f, ss = 0.f;
    #pragma unroll
    for (int j = 0; j < CPL; j++) {
        const float dx = c[j].x - g.x;
        const float dy = c[j].y - g.y;
        f[j] = sc * sqrtf(fmaf(dx, dx, dy * dy));
        const float ef = expf(-f[j]);
        zs += ef;
        ss  = fmaf(ef, o[j], ss);
        zo += expf(o[j]);
        os[j] = sortable(o[j]);
    }

    // warp partial sums (fused butterfly), lane0 -> smem
    #pragma unroll
    for (int off = 16; off; off >>= 1) {
        zs += __shfl_xor_sync(0xffffffffu, zs, off);
        zo += __shfl_xor_sync(0xffffffffu, zo, off);
        ss += __shfl_xor_sync(0xffffffffu, ss, off);
    }
    if (lane == 0) {
        sm_sum[s][ws][0] = zs; sm_sum[s][ws][1] = zo; sm_sum[s][ws][2] = ss;
    }

    // ---- lane-local sorted list (desc) of this lane's 4 values ----
    unsigned t0 = 0, t1 = 0, t2 = 0, t3 = 0;
    #pragma unroll
    for (int j = 0; j < CPL; j++) {
        unsigned x = os[j], a;
        a = max(t0, x); x = min(t0, x); t0 = a;
        a = max(t1, x); x = min(t1, x); t1 = a;
        a = max(t2, x); x = min(t2, x); t2 = a;
        t3 = max(t3, x);
    }

    // ---- 6 warp pops via REDUX -> this warp's top-6 (desc) ----
    #pragma unroll
    for (int r = 0; r < MAX_GUESSES; r++) {
        const unsigned m = __reduce_max_sync(0xffffffffu, t0);
        if (lane == 0) sm_top[s][ws][r] = m;
        if (t0 == m) { t0 = t1; t1 = t2; t2 = t3; t3 = 0; }
    }
    __syncthreads();

    // ---- merge 4 warps' top-6 lists -> theta = 6th largest of sample ----
    unsigned m0 = 0, m1 = 0, m2 = 0, m3 = 0, m4 = 0, m5 = 0;
    #pragma unroll
    for (int w = 0; w < WPS; w++) {
        #pragma unroll
        for (int r = 0; r < MAX_GUESSES; r++) {
            unsigned x = sm_top[s][w][r], a;
            a = max(m0, x); x = min(m0, x); m0 = a;
            a = max(m1, x); x = min(m1, x); m1 = a;
            a = max(m2, x); x = min(m2, x); m2 = a;
            a = max(m3, x); x = min(m3, x); m3 = a;
            a = max(m4, x); x = min(m4, x); m4 = a;
            m5 = max(m5, x);
        }
    }
    const unsigned theta = m5;

    // ---- per-warp minFDE among {os >= theta}; f>=0 so raw bits order ----
    float minf = 3.4e38f;
    #pragma unroll
    for (int j = 0; j < CPL; j++)
        if (os[j] >= theta) minf = fminf(minf, f[j]);
    const unsigned mfb = __reduce_min_sync(0xffffffffu, __float_as_uint(minf));
    if (lane == 0) sm_minf[s][ws] = mfb;
    __syncthreads();

    // ---- per-sample epilogue (one lane per sample) ----
    if (ws == 0 && lane == 0) {
        float Zs = 0.f, Zo = 0.f, Ss = 0.f;
        unsigned mn = 0xffffffffu;
        #pragma unroll
        for (int w = 0; w < WPS; w++) {
            Zs += sm_sum[s][w][0];
            Zo += sm_sum[s][w][1];
            Ss += sm_sum[s][w][2];
            mn  = min(mn, sm_minf[s][w]);
        }
        const float minF = __uint_as_float(mn);
        const float cls  = logf(Zo) - Ss / Zs;
        g_loss[b] = cls + fmaxf(minF - MISS_THRESH, 0.0f);
    }

    // ---- fused deterministic tail reduction (last CTA to finish) ----
    __shared__ bool  s_last;
    __shared__ float sm_red[NTH / 32];
    __syncthreads();
    if (threadIdx.x == 0) {
        __threadfence();
        const unsigned p = atomicAdd(&g_cnt, 1u);
        s_last = (p == (unsigned)(gridDim.x - 1));
    }
    __syncthreads();
    if (s_last) {
        float acc = 0.f;
        #pragma unroll
        for (int i = 0; i < B_DIM / NTH; i++)
            acc += __ldcg(&g_loss[threadIdx.x + i * NTH]);   // L1-bypass
        #pragma unroll
        for (int off = 16; off; off >>= 1)
            acc += __shfl_xor_sync(0xffffffffu, acc, off);
        if (lane == 0) sm_red[wid] = acc;
        __syncthreads();
        if (threadIdx.x < 32) {
            acc = (threadIdx.x < NTH / 32) ? sm_red[threadIdx.x] : 0.f;
            #pragma unroll
            for (int off = 4; off; off >>= 1)
                acc += __shfl_xor_sync(0xffffffffu, acc, off);
            if (threadIdx.x == 0) {
                out[0] = acc * (1.0f / (float)B_DIM);
                g_cnt = 0;   // reset for next graph replay
            }
        }
    }
}

extern "C" void kernel_launch(void* const* d_in, const int* in_sizes, int n_in,
                              void* d_out, int out_size)
{
    const float* out_scores = (const float*)d_in[0];   // (B*K, 1)
    const float* pred_cand  = (const float*)d_in[1];   // (B, K, T, 2)
    const float* pred_gt    = (const float*)d_in[2];   // (B, T, 2)
    const float* scales     = (const float*)d_in[3];   // (B,)
    float* out = (float*)d_out;

    score_classify_fused<<<GRID_DIM, NTH>>>(out_scores, pred_cand, pred_gt, scales, out);
}